// round 8
// baseline (speedup 1.0000x reference)
#include <cuda_runtime.h>
#include <cuda_bf16.h>
#include <cstdint>

// ---------------- problem constants ----------------
#define MDIM 16384          // B*S
#define KD   1024           // d_model
#define NELEM ((size_t)MDIM * KD)
#define WELEM ((size_t)KD * KD)

// GEMM tiling: CTA 256x128, 16 warps (4x4), warp tile 64x32, BK=32 (4 k8-steps)
#define TMC 256
#define TN  128
#define BK  32
#define NCH (KD / BK)                 // 32 chunks
#define PITCHB 144                    // smem row pitch bytes (128B data + 16B pad)
#define A_BYTES (256 * PITCHB)        // 36864
#define B_BYTES (128 * PITCHB)        // 18432
#define STAGE_BYTES (A_BYTES + B_BYTES)  // 55296
#define STAGES 4
#define SMEM_DYN (STAGES * STAGE_BYTES)  // 221184
#define NTHR 512

// ---------------- device scratch ----------------
__device__ float g_aq[NELEM], g_ak[NELEM], g_av[NELEM];   // tf32-rounded activations
__device__ float g_w[4][WELEM];                            // tf32-rounded weights
__device__ float g_q[NELEM], g_k[NELEM], g_v[NELEM];       // projections
__device__ float g_x[NELEM];                               // attn out (tf32-rounded)

// ---------------- PTX helpers ----------------
__device__ __forceinline__ uint32_t smem_u32(const void* p) {
    uint32_t a;
    asm("{ .reg .u64 t; cvta.to.shared.u64 t, %1; cvt.u32.u64 %0, t; }" : "=r"(a) : "l"(p));
    return a;
}
__device__ __forceinline__ void cp16(uint32_t dst, const void* src) {
    asm volatile("cp.async.cg.shared.global [%0], [%1], 16;" :: "r"(dst), "l"(src));
}
__device__ __forceinline__ void cp_commit() { asm volatile("cp.async.commit_group;"); }
__device__ __forceinline__ void ldm_x4(uint32_t r[4], uint32_t addr) {
    asm volatile("ldmatrix.sync.aligned.m8n8.x4.shared.b16 {%0,%1,%2,%3}, [%4];"
                 : "=r"(r[0]), "=r"(r[1]), "=r"(r[2]), "=r"(r[3]) : "r"(addr));
}
__device__ __forceinline__ void mma_tf32(float c[4], const uint32_t a[4],
                                         uint32_t b0, uint32_t b1) {
    asm volatile(
        "mma.sync.aligned.m16n8k8.row.col.f32.tf32.tf32.f32 "
        "{%0,%1,%2,%3}, {%4,%5,%6,%7}, {%8,%9}, {%0,%1,%2,%3};"
        : "+f"(c[0]), "+f"(c[1]), "+f"(c[2]), "+f"(c[3])
        : "r"(a[0]), "r"(a[1]), "r"(a[2]), "r"(a[3]), "r"(b0), "r"(b1));
}
__device__ __forceinline__ float tf32r(float x) {
    uint32_t u;
    asm("cvt.rna.tf32.f32 %0, %1;" : "=r"(u) : "f"(x));
    return __uint_as_float(u);
}

// ---------------- GEMM: C[16384,1024] = A*W^T + bias (tf32 single-pass) ----------------
// A: [MDIM, KD] fp32 (tf32-rounded). W: [KD, KD] fp32 (tf32-rounded), row = out-feature.
__device__ __forceinline__ void tf32_gemm_body(
    const float* __restrict__ A, const float* __restrict__ W,
    const float* __restrict__ bias, float* __restrict__ C)
{
    extern __shared__ char dynsm[];
    const uint32_t sb = smem_u32(dynsm);

    const int t    = threadIdx.x;
    const int lane = t & 31;
    const int wid  = t >> 5;
    const int wm   = (wid >> 2) * 64;    // warp m offset (0..192)
    const int wn   = (wid & 3) * 32;     // warp n offset (0..96)
    const int m0   = blockIdx.y * TMC;
    const int n0   = blockIdx.x * TN;

    const char* pA = (const char*)A;
    const char* pW = (const char*)W;

    float acc[4][4][4];
#pragma unroll
    for (int i = 0; i < 4; i++)
#pragma unroll
        for (int j = 0; j < 4; j++)
#pragma unroll
            for (int r = 0; r < 4; r++) acc[i][j][r] = 0.f;

    // cp.async slots: A = 2048 x 16B (256 rows x 8), B = 1024 x 16B (128 rows x 8)
    const int ar[4] = {t >> 3, (t + 512) >> 3, (t + 1024) >> 3, (t + 1536) >> 3};
    const int aq    = t & 7;
    const int br[2] = {t >> 3, (t + 512) >> 3};

    auto load_chunk = [&](int c, int buf) {
        const uint32_t s  = sb + (uint32_t)buf * STAGE_BYTES;
        const uint32_t sB = s + A_BYTES;
        const size_t kb = (size_t)c * 128;        // 32 floats = 128B per chunk-row
#pragma unroll
        for (int i = 0; i < 4; i++)
            cp16(s + (uint32_t)(ar[i] * PITCHB + aq * 16),
                 pA + (size_t)(m0 + ar[i]) * 4096 + kb + aq * 16);
#pragma unroll
        for (int i = 0; i < 2; i++)
            cp16(sB + (uint32_t)(br[i] * PITCHB + aq * 16),
                 pW + (size_t)(n0 + br[i]) * 4096 + kb + aq * 16);
    };

    // prologue: 3 chunks in flight
    load_chunk(0, 0); cp_commit();
    load_chunk(1, 1); cp_commit();
    load_chunk(2, 2); cp_commit();

    // ldmatrix per-lane address pieces
    const int g  = lane >> 3;
    const int r8 = lane & 7;
    const uint32_t aBase = (uint32_t)((wm + (g & 1) * 8 + r8) * PITCHB + (g >> 1) * 16);
    const uint32_t bBase = (uint32_t)((wn + (g >> 1) * 8 + r8) * PITCHB + (g & 1) * 16);

#pragma unroll 1
    for (int c = 0; c < NCH; c++) {
        asm volatile("cp.async.wait_group 2;");
        __syncthreads();

        // issue next loads into the buffer consumed LAST iteration (safe post-sync)
        if (c + 3 < NCH) load_chunk(c + 3, (c + 3) % STAGES);
        cp_commit();

        const uint32_t s  = sb + (uint32_t)(c % STAGES) * STAGE_BYTES;
        const uint32_t sA = s;
        const uint32_t sB = s + A_BYTES;

#pragma unroll
        for (int ks = 0; ks < 4; ks++) {
            const uint32_t kb = (uint32_t)(ks * 32);
            uint32_t bf[2][4];
            ldm_x4(bf[0], sB + bBase + kb);
            ldm_x4(bf[1], sB + bBase + (uint32_t)(16 * PITCHB) + kb);
            // A-fragment 2-ring: prefetch mt+1 while issuing MMAs of mt
            uint32_t af[2][4];
            ldm_x4(af[0], sA + aBase + kb);
#pragma unroll
            for (int mt = 0; mt < 4; mt++) {
                if (mt < 3)
                    ldm_x4(af[(mt + 1) & 1],
                           sA + aBase + (uint32_t)((mt + 1) * 16 * PITCHB) + kb);
                const uint32_t* am = af[mt & 1];
#pragma unroll
                for (int j = 0; j < 4; j++) {
                    const int p = j >> 1, e = (j & 1) * 2;
                    mma_tf32(acc[mt][j], am, bf[p][e], bf[p][e + 1]);
                }
            }
        }
    }

    // epilogue: bias + store
    const int tr = lane >> 2;
    const int tc = (lane & 3) * 2;
#pragma unroll
    for (int mt = 0; mt < 4; mt++) {
        const int gr = m0 + wm + mt * 16 + tr;
        float* row0 = C + (size_t)gr * KD + n0 + wn;
        float* row1 = row0 + 8 * KD;
#pragma unroll
        for (int j = 0; j < 4; j++) {
            const int gc = wn + j * 8 + tc;
            float2 bb = *(const float2*)(bias + n0 + gc);
            float2 o0, o1;
            o0.x = acc[mt][j][0] + bb.x;  o0.y = acc[mt][j][1] + bb.y;
            o1.x = acc[mt][j][2] + bb.x;  o1.y = acc[mt][j][3] + bb.y;
            *(float2*)(row0 + j * 8 + tc) = o0;
            *(float2*)(row1 + j * 8 + tc) = o1;
        }
    }
}

__global__ __launch_bounds__(NTHR, 1)
void qkv_mma_kernel(const float* __restrict__ bq, const float* __restrict__ bk,
                    const float* __restrict__ bv) {
    const int z = blockIdx.z;
    const float* A = (z == 0) ? g_aq : (z == 1) ? g_ak : g_av;
    const float* bias = (z == 0) ? bq : (z == 1) ? bk : bv;
    float* C = (z == 0) ? g_q : (z == 1) ? g_k : g_v;
    tf32_gemm_body(A, g_w[z], bias, C);
}

__global__ __launch_bounds__(NTHR, 1)
void out_mma_kernel(const float* __restrict__ bo, float* __restrict__ out) {
    tf32_gemm_body(g_x, g_w[3], bo, out);
}

// ---------------- tf32 rounding copy passes ----------------
__device__ __forceinline__ void round4(const float4 v, float* dst, size_t i4) {
    float4 o;
    o.x = tf32r(v.x); o.y = tf32r(v.y); o.z = tf32r(v.z); o.w = tf32r(v.w);
    ((float4*)dst)[i4] = o;
}

__global__ __launch_bounds__(256)
void round_act_kernel(const float* __restrict__ q, const float* __restrict__ k,
                      const float* __restrict__ v) {
    const int z = blockIdx.y;
    const float* src = (z == 0) ? q : (z == 1) ? k : v;
    float* dst = (z == 0) ? g_aq : (z == 1) ? g_ak : g_av;
    const size_t n4 = NELEM / 4;
    const size_t stride = (size_t)gridDim.x * blockDim.x;
    for (size_t i = (size_t)blockIdx.x * blockDim.x + threadIdx.x; i < n4; i += stride)
        round4(((const float4*)src)[i], dst, i);
}

__global__ __launch_bounds__(256)
void round_w_kernel(const float* __restrict__ wq, const float* __restrict__ wk,
                    const float* __restrict__ wv, const float* __restrict__ wo) {
    const int z = blockIdx.y;
    const float* src = (z == 0) ? wq : (z == 1) ? wk : (z == 2) ? wv : wo;
    float* dst = g_w[z];
    const size_t n4 = WELEM / 4;
    const size_t stride = (size_t)gridDim.x * blockDim.x;
    for (size_t i = (size_t)blockIdx.x * blockDim.x + threadIdx.x; i < n4; i += stride)
        round4(((const float4*)src)[i], dst, i);
}

// ---------------- per-token head attention, fused tf32 rounding ----------------
__global__ __launch_bounds__(256)
void attn_kernel() {
    const int token = blockIdx.x;
    const int b = token >> 12;
    const int s = token & 4095;
    __shared__ float qs[16 * 64];
    __shared__ float ks[16 * 68];
    __shared__ float vs[16 * 64];
    __shared__ float at[16][16];

    const int t = threadIdx.x;
    const size_t base = (size_t)token * 1024;
    {
        float4 qv = ((const float4*)(g_q + base))[t];
        float4 kv = ((const float4*)(g_k + base))[t];
        float4 vv = ((const float4*)(g_v + base))[t];
        ((float4*)qs)[t] = qv;
        ((float4*)vs)[t] = vv;
        const int gg = t >> 4, dd = (t & 15) << 2;
        *(float4*)(ks + gg * 68 + dd) = kv;
    }
    __syncthreads();

    const int h = t >> 4, g = t & 15;
    const float* qr = qs + h * 64;
    const float* kr = ks + g * 68;
    float acc = 0.f;
#pragma unroll
    for (int d = 0; d < 64; d += 4) {
        float4 qa = *(const float4*)(qr + d);
        float4 ka = *(const float4*)(kr + d);
        acc += qa.x * ka.x + qa.y * ka.y + qa.z * ka.z + qa.w * ka.w;
    }
    float sc = acc * 0.125f;
    float mx = sc;
#pragma unroll
    for (int d = 8; d; d >>= 1) mx = fmaxf(mx, __shfl_xor_sync(0xffffffffu, mx, d));
    float p = __expf(sc - mx);
    float sm = p;
#pragma unroll
    for (int d = 8; d; d >>= 1) sm += __shfl_xor_sync(0xffffffffu, sm, d);
    at[h][g] = p / sm;
    __syncthreads();

    const int h2 = t >> 4, db = (t & 15) << 2;
    float4 o = make_float4(0.f, 0.f, 0.f, 0.f);
#pragma unroll
    for (int gg = 0; gg < 16; gg++) {
        const float w = at[h2][gg];
        const float* vr = vs + gg * 64 + db;
        o.x += w * vr[0];
        o.y += w * vr[1];
        o.z += w * vr[2];
        o.w += w * vr[3];
    }
    // scrambled layout + tf32 rounding (feeds the tf32 out-GEMM directly)
    const size_t row = (size_t)b * 4096 + (size_t)h2 * 256 + (s >> 4);
    const size_t idx = row * 1024 + (s & 15) * 64 + db;
    float4 ro;
    ro.x = tf32r(o.x); ro.y = tf32r(o.y); ro.z = tf32r(o.z); ro.w = tf32r(o.w);
    *(float4*)(g_x + idx) = ro;
}

// ---------------- launch ----------------
extern "C" void kernel_launch(void* const* d_in, const int* in_sizes, int n_in,
                              void* d_out, int out_size) {
    (void)in_sizes; (void)n_in; (void)out_size;
    const float* query = (const float*)d_in[0];
    const float* key   = (const float*)d_in[1];
    const float* value = (const float*)d_in[2];
    const float* Wq = (const float*)d_in[3];
    const float* bq = (const float*)d_in[4];
    const float* Wk = (const float*)d_in[5];
    const float* bk = (const float*)d_in[6];
    const float* Wv = (const float*)d_in[7];
    const float* bv = (const float*)d_in[8];
    const float* Wo = (const float*)d_in[9];
    const float* bo = (const float*)d_in[10];
    float* out = (float*)d_out;

    cudaFuncSetAttribute(qkv_mma_kernel, cudaFuncAttributeMaxDynamicSharedMemorySize, SMEM_DYN);
    cudaFuncSetAttribute(out_mma_kernel, cudaFuncAttributeMaxDynamicSharedMemorySize, SMEM_DYN);

    round_act_kernel<<<dim3(4096, 3), 256>>>(query, key, value);
    round_w_kernel<<<dim3(1024, 4), 256>>>(Wq, Wk, Wv, Wo);
    qkv_mma_kernel<<<dim3(KD / TN, MDIM / TMC, 3), NTHR, SMEM_DYN>>>(bq, bk, bv);
    attn_kernel<<<MDIM, 256>>>();
    out_mma_kernel<<<dim3(KD / TN, MDIM / TMC, 1), NTHR, SMEM_DYN>>>(bo, out);
}

// round 9
// speedup vs baseline: 1.1319x; 1.1319x over previous
#include <cuda_runtime.h>
#include <cuda_bf16.h>
#include <cstdint>

// ---------------- problem constants ----------------
#define MDIM 16384          // B*S
#define KD   1024           // d_model
#define NELEM ((size_t)MDIM * KD)
#define WELEM ((size_t)KD * KD)

// GEMM tiling: CTA 128x128, 8 warps (2x4), warp tile 64x32, BK=32 (4 k8-steps)
// 2 CTAs per SM for inter-CTA latency hiding.
#define TMC 128
#define TN  128
#define BK  32
#define NCH (KD / BK)                 // 32 chunks
#define PITCHB 144                    // smem row pitch bytes (128B data + 16B pad)
#define A_BYTES (128 * PITCHB)        // 18432
#define B_BYTES (128 * PITCHB)        // 18432
#define STAGE_BYTES (A_BYTES + B_BYTES)  // 36864
#define STAGES 3
#define SMEM_DYN (STAGES * STAGE_BYTES)  // 110592 (x2 CTAs = 221184 <= 227KB)
#define NTHR 256

// ---------------- device scratch ----------------
__device__ float g_aq[NELEM], g_ak[NELEM], g_av[NELEM];   // tf32-rounded activations
__device__ float g_w[4][WELEM];                            // tf32-rounded weights
__device__ float g_q[NELEM], g_k[NELEM], g_v[NELEM];       // projections
__device__ float g_x[NELEM];                               // attn out (tf32-rounded)

// ---------------- PTX helpers ----------------
__device__ __forceinline__ uint32_t smem_u32(const void* p) {
    uint32_t a;
    asm("{ .reg .u64 t; cvta.to.shared.u64 t, %1; cvt.u32.u64 %0, t; }" : "=r"(a) : "l"(p));
    return a;
}
__device__ __forceinline__ void cp16(uint32_t dst, const void* src) {
    asm volatile("cp.async.cg.shared.global [%0], [%1], 16;" :: "r"(dst), "l"(src));
}
__device__ __forceinline__ void cp_commit() { asm volatile("cp.async.commit_group;"); }
__device__ __forceinline__ void ldm_x4(uint32_t r[4], uint32_t addr) {
    asm volatile("ldmatrix.sync.aligned.m8n8.x4.shared.b16 {%0,%1,%2,%3}, [%4];"
                 : "=r"(r[0]), "=r"(r[1]), "=r"(r[2]), "=r"(r[3]) : "r"(addr));
}
__device__ __forceinline__ void mma_tf32(float c[4], const uint32_t a[4],
                                         uint32_t b0, uint32_t b1) {
    asm volatile(
        "mma.sync.aligned.m16n8k8.row.col.f32.tf32.tf32.f32 "
        "{%0,%1,%2,%3}, {%4,%5,%6,%7}, {%8,%9}, {%0,%1,%2,%3};"
        : "+f"(c[0]), "+f"(c[1]), "+f"(c[2]), "+f"(c[3])
        : "r"(a[0]), "r"(a[1]), "r"(a[2]), "r"(a[3]), "r"(b0), "r"(b1));
}
__device__ __forceinline__ float tf32r(float x) {
    uint32_t u;
    asm("cvt.rna.tf32.f32 %0, %1;" : "=r"(u) : "f"(x));
    return __uint_as_float(u);
}

// ---------------- GEMM: C[16384,1024] = A*W^T + bias (tf32 single-pass) ----------------
// A: [MDIM, KD] fp32 (tf32-rounded). W: [KD, KD] fp32 (tf32-rounded), row = out-feature.
__device__ __forceinline__ void tf32_gemm_body(
    const float* __restrict__ A, const float* __restrict__ W,
    const float* __restrict__ bias, float* __restrict__ C)
{
    extern __shared__ char dynsm[];
    const uint32_t sb = smem_u32(dynsm);

    const int t    = threadIdx.x;
    const int lane = t & 31;
    const int wid  = t >> 5;
    const int wm   = (wid >> 2) * 64;    // warp m offset (0/64)
    const int wn   = (wid & 3) * 32;     // warp n offset (0..96)
    const int m0   = blockIdx.y * TMC;
    const int n0   = blockIdx.x * TN;

    const char* pA = (const char*)A;
    const char* pW = (const char*)W;

    float acc[4][4][4];
#pragma unroll
    for (int i = 0; i < 4; i++)
#pragma unroll
        for (int j = 0; j < 4; j++)
#pragma unroll
            for (int r = 0; r < 4; r++) acc[i][j][r] = 0.f;

    // cp.async slots: A = 1024 x 16B (128 rows x 8), B = 1024 x 16B; 8 cp16/thread
    const int sl[4] = {t, t + 256, t + 512, t + 768};

    auto load_chunk = [&](int c, int buf) {
        const uint32_t s  = sb + (uint32_t)buf * STAGE_BYTES;
        const uint32_t sB = s + A_BYTES;
        const size_t kb = (size_t)c * 128;        // 32 floats = 128B per chunk-row
#pragma unroll
        for (int i = 0; i < 4; i++) {
            const int r = sl[i] >> 3, q = sl[i] & 7;
            const uint32_t off = (uint32_t)(r * PITCHB + q * 16);
            cp16(s  + off, pA + (size_t)(m0 + r) * 4096 + kb + q * 16);
            cp16(sB + off, pW + (size_t)(n0 + r) * 4096 + kb + q * 16);
        }
    };

    // prologue: 2 chunks in flight (3rd buffer free for single-sync rotation)
    load_chunk(0, 0); cp_commit();
    load_chunk(1, 1); cp_commit();

    // ldmatrix per-lane address pieces
    const int g  = lane >> 3;
    const int r8 = lane & 7;
    const uint32_t aBase = (uint32_t)((wm + (g & 1) * 8 + r8) * PITCHB + (g >> 1) * 16);
    const uint32_t bBase = (uint32_t)((wn + (g >> 1) * 8 + r8) * PITCHB + (g & 1) * 16);

#pragma unroll 1
    for (int c = 0; c < NCH; c++) {
        asm volatile("cp.async.wait_group 1;");
        __syncthreads();

        // issue next loads into the buffer consumed LAST iteration (safe post-sync)
        if (c + 2 < NCH) load_chunk(c + 2, (c + 2) % STAGES);
        cp_commit();

        const uint32_t s  = sb + (uint32_t)(c % STAGES) * STAGE_BYTES;
        const uint32_t sA = s;
        const uint32_t sB = s + A_BYTES;

#pragma unroll
        for (int ks = 0; ks < 4; ks++) {
            const uint32_t kb = (uint32_t)(ks * 32);
            uint32_t af[4][4], bf[2][4];
#pragma unroll
            for (int mt = 0; mt < 4; mt++)
                ldm_x4(af[mt], sA + aBase + (uint32_t)(mt * 16 * PITCHB) + kb);
#pragma unroll
            for (int nn = 0; nn < 2; nn++)
                ldm_x4(bf[nn], sB + bBase + (uint32_t)(nn * 16 * PITCHB) + kb);
#pragma unroll
            for (int mt = 0; mt < 4; mt++) {
#pragma unroll
                for (int j = 0; j < 4; j++) {
                    const int p = j >> 1, e = (j & 1) * 2;
                    mma_tf32(acc[mt][j], af[mt], bf[p][e], bf[p][e + 1]);
                }
            }
        }
    }

    // epilogue: bias + store
    const int tr = lane >> 2;
    const int tc = (lane & 3) * 2;
#pragma unroll
    for (int mt = 0; mt < 4; mt++) {
        const int gr = m0 + wm + mt * 16 + tr;
        float* row0 = C + (size_t)gr * KD + n0 + wn;
        float* row1 = row0 + 8 * KD;
#pragma unroll
        for (int j = 0; j < 4; j++) {
            const int gc = wn + j * 8 + tc;
            float2 bb = *(const float2*)(bias + n0 + gc);
            float2 o0, o1;
            o0.x = acc[mt][j][0] + bb.x;  o0.y = acc[mt][j][1] + bb.y;
            o1.x = acc[mt][j][2] + bb.x;  o1.y = acc[mt][j][3] + bb.y;
            *(float2*)(row0 + j * 8 + tc) = o0;
            *(float2*)(row1 + j * 8 + tc) = o1;
        }
    }
}

__global__ __launch_bounds__(NTHR, 2)
void qkv_mma_kernel(const float* __restrict__ bq, const float* __restrict__ bk,
                    const float* __restrict__ bv) {
    const int z = blockIdx.z;
    const float* A = (z == 0) ? g_aq : (z == 1) ? g_ak : g_av;
    const float* bias = (z == 0) ? bq : (z == 1) ? bk : bv;
    float* C = (z == 0) ? g_q : (z == 1) ? g_k : g_v;
    tf32_gemm_body(A, g_w[z], bias, C);
}

__global__ __launch_bounds__(NTHR, 2)
void out_mma_kernel(const float* __restrict__ bo, float* __restrict__ out) {
    tf32_gemm_body(g_x, g_w[3], bo, out);
}

// ---------------- tf32 rounding copy passes ----------------
__device__ __forceinline__ void round4(const float4 v, float* dst, size_t i4) {
    float4 o;
    o.x = tf32r(v.x); o.y = tf32r(v.y); o.z = tf32r(v.z); o.w = tf32r(v.w);
    ((float4*)dst)[i4] = o;
}

__global__ __launch_bounds__(256)
void round_act_kernel(const float* __restrict__ q, const float* __restrict__ k,
                      const float* __restrict__ v) {
    const int z = blockIdx.y;
    const float* src = (z == 0) ? q : (z == 1) ? k : v;
    float* dst = (z == 0) ? g_aq : (z == 1) ? g_ak : g_av;
    const size_t n4 = NELEM / 4;
    const size_t stride = (size_t)gridDim.x * blockDim.x;
    for (size_t i = (size_t)blockIdx.x * blockDim.x + threadIdx.x; i < n4; i += stride)
        round4(((const float4*)src)[i], dst, i);
}

__global__ __launch_bounds__(256)
void round_w_kernel(const float* __restrict__ wq, const float* __restrict__ wk,
                    const float* __restrict__ wv, const float* __restrict__ wo) {
    const int z = blockIdx.y;
    const float* src = (z == 0) ? wq : (z == 1) ? wk : (z == 2) ? wv : wo;
    float* dst = g_w[z];
    const size_t n4 = WELEM / 4;
    const size_t stride = (size_t)gridDim.x * blockDim.x;
    for (size_t i = (size_t)blockIdx.x * blockDim.x + threadIdx.x; i < n4; i += stride)
        round4(((const float4*)src)[i], dst, i);
}

// ---------------- per-token head attention, fused tf32 rounding ----------------
__global__ __launch_bounds__(256)
void attn_kernel() {
    const int token = blockIdx.x;
    const int b = token >> 12;
    const int s = token & 4095;
    __shared__ float qs[16 * 64];
    __shared__ float ks[16 * 68];
    __shared__ float vs[16 * 64];
    __shared__ float at[16][16];

    const int t = threadIdx.x;
    const size_t base = (size_t)token * 1024;
    {
        float4 qv = ((const float4*)(g_q + base))[t];
        float4 kv = ((const float4*)(g_k + base))[t];
        float4 vv = ((const float4*)(g_v + base))[t];
        ((float4*)qs)[t] = qv;
        ((float4*)vs)[t] = vv;
        const int gg = t >> 4, dd = (t & 15) << 2;
        *(float4*)(ks + gg * 68 + dd) = kv;
    }
    __syncthreads();

    const int h = t >> 4, g = t & 15;
    const float* qr = qs + h * 64;
    const float* kr = ks + g * 68;
    float acc = 0.f;
#pragma unroll
    for (int d = 0; d < 64; d += 4) {
        float4 qa = *(const float4*)(qr + d);
        float4 ka = *(const float4*)(kr + d);
        acc += qa.x * ka.x + qa.y * ka.y + qa.z * ka.z + qa.w * ka.w;
    }
    float sc = acc * 0.125f;
    float mx = sc;
#pragma unroll
    for (int d = 8; d; d >>= 1) mx = fmaxf(mx, __shfl_xor_sync(0xffffffffu, mx, d));
    float p = __expf(sc - mx);
    float sm = p;
#pragma unroll
    for (int d = 8; d; d >>= 1) sm += __shfl_xor_sync(0xffffffffu, sm, d);
    at[h][g] = p / sm;
    __syncthreads();

    const int h2 = t >> 4, db = (t & 15) << 2;
    float4 o = make_float4(0.f, 0.f, 0.f, 0.f);
#pragma unroll
    for (int gg = 0; gg < 16; gg++) {
        const float w = at[h2][gg];
        const float* vr = vs + gg * 64 + db;
        o.x += w * vr[0];
        o.y += w * vr[1];
        o.z += w * vr[2];
        o.w += w * vr[3];
    }
    // scrambled layout + tf32 rounding (feeds the tf32 out-GEMM directly)
    const size_t row = (size_t)b * 4096 + (size_t)h2 * 256 + (s >> 4);
    const size_t idx = row * 1024 + (s & 15) * 64 + db;
    float4 ro;
    ro.x = tf32r(o.x); ro.y = tf32r(o.y); ro.z = tf32r(o.z); ro.w = tf32r(o.w);
    *(float4*)(g_x + idx) = ro;
}

// ---------------- launch ----------------
extern "C" void kernel_launch(void* const* d_in, const int* in_sizes, int n_in,
                              void* d_out, int out_size) {
    (void)in_sizes; (void)n_in; (void)out_size;
    const float* query = (const float*)d_in[0];
    const float* key   = (const float*)d_in[1];
    const float* value = (const float*)d_in[2];
    const float* Wq = (const float*)d_in[3];
    const float* bq = (const float*)d_in[4];
    const float* Wk = (const float*)d_in[5];
    const float* bk = (const float*)d_in[6];
    const float* Wv = (const float*)d_in[7];
    const float* bv = (const float*)d_in[8];
    const float* Wo = (const float*)d_in[9];
    const float* bo = (const float*)d_in[10];
    float* out = (float*)d_out;

    cudaFuncSetAttribute(qkv_mma_kernel, cudaFuncAttributeMaxDynamicSharedMemorySize, SMEM_DYN);
    cudaFuncSetAttribute(out_mma_kernel, cudaFuncAttributeMaxDynamicSharedMemorySize, SMEM_DYN);

    round_act_kernel<<<dim3(4096, 3), 256>>>(query, key, value);
    round_w_kernel<<<dim3(1024, 4), 256>>>(Wq, Wk, Wv, Wo);
    qkv_mma_kernel<<<dim3(KD / TN, MDIM / TMC, 3), NTHR, SMEM_DYN>>>(bq, bk, bv);
    attn_kernel<<<MDIM, 256>>>();
    out_mma_kernel<<<dim3(KD / TN, MDIM / TMC, 1), NTHR, SMEM_DYN>>>(bo, out);
}